// round 16
// baseline (speedup 1.0000x reference)
#include <cuda_runtime.h>
#include <cuda_bf16.h>
#include <cstdint>

// ---------------------------------------------------------------------------
// SAMMCodebook.encode on GB300 (sm_103a) — single-term bf16 HMMA + exact
// fp32 refinement (margin-gated, TAU=1.0).
//   h:[65536,1024]f32, cb:[512,1024]f32 -> float out[65536]
//   argmin_k ||h-c_k||^2 == argmin_k (0.5||c_k||^2 - <h,c_k>)
//
// R15 analysis: 3-term split HMMA hit ~140 TF/s -> HMMA issue-rate bound.
// This round: 1 bf16 MMA term (3x fewer MMAs), TAU widened 0.05 -> 1.0
// (bf16 dot noise sigma ~0.07; ~2% of rows refined exactly in fp32).
// h pre-converted to packed/swizzled bf16 once (g_hbf); both operands are
// staged with pure cp.async and read as conflict-free LDS.64 fragments.
// ---------------------------------------------------------------------------

__device__ float    g_csq[512];
__device__ unsigned g_cbhi[512 * 512];         // swizzled bf16 pairs [k][512]
__device__ unsigned g_hbf[65536u * 512u];      // swizzled bf16 pairs [n][512]
__device__ float    g_margin[65536];

__device__ __forceinline__ uint32_t pack_bf(float a, float b) {
    return (uint32_t)__bfloat16_as_ushort(__float2bfloat16(a)) |
           ((uint32_t)__bfloat16_as_ushort(__float2bfloat16(b)) << 16);
}
// u32 logical col c (0..15) -> stored position, keyed by matrix row.
// PERM makes MMA fragment pairs (c, c+4) adjacent; XOR-swizzle (granule ^
// row&7) makes the LDS.64 fragment pattern bank-conflict-free.
__device__ __forceinline__ int qpos(int c, int r) {
    int p = ((c & 3) << 1) | ((c >> 2) & 1) | (c & 8);
    return (((p >> 1) ^ (r & 7)) << 1) | (p & 1);
}

__device__ __forceinline__ uint32_t smem_u32(const void* p) {
    uint32_t a;
    asm("{ .reg .u64 t; cvta.to.shared.u64 t, %1; cvt.u32.u64 %0, t; }"
        : "=r"(a) : "l"(p));
    return a;
}
#define CPASYNC16(dst, src) \
    asm volatile("cp.async.cg.shared.global [%0], [%1], 16;" \
                 :: "r"(dst), "l"(src) : "memory")
#define CPCOMMIT() asm volatile("cp.async.commit_group;" ::: "memory")

// ---- phase 0a: csq + swizzled bf16 pack of codebook ------------------------
__global__ void prep_cb(const float* __restrict__ cb) {
    int k = blockIdx.x;               // 512 blocks, one per codeword
    int t = threadIdx.x;              // 256 threads
    float4 v = reinterpret_cast<const float4*>(cb + (size_t)k * 1024)[t];
    float s = v.x * v.x + v.y * v.y + v.z * v.z + v.w * v.w;
    #pragma unroll
    for (int o = 16; o; o >>= 1) s += __shfl_xor_sync(0xffffffffu, s, o);
    __shared__ float ws[8];
    if ((t & 31) == 0) ws[t >> 5] = s;
    __syncthreads();
    if (t == 0) {
        float tot = 0.f;
        #pragma unroll
        for (int w = 0; w < 8; w++) tot += ws[w];
        g_csq[k] = tot;
    }
    #pragma unroll
    for (int it = 0; it < 2; it++) {
        int lin = t + 256 * it;       // (chunk, u32 col)
        int ch = lin >> 4, c = lin & 15;
        float a = cb[(size_t)k * 1024 + 32 * ch + 2 * c];
        float b = cb[(size_t)k * 1024 + 32 * ch + 2 * c + 1];
        g_cbhi[k * 512 + ch * 16 + qpos(c, k)] = pack_bf(a, b);
    }
}

// ---- phase 0b: swizzled bf16 pack of h -------------------------------------
__global__ void prep_h(const float* __restrict__ h) {
    int r  = blockIdx.x * 8 + (threadIdx.x >> 5);
    int ch = threadIdx.x & 31;
    const float* src = h + (size_t)r * 1024 + 32 * ch;
    unsigned* dst = g_hbf + (size_t)r * 512 + ch * 16;
    #pragma unroll
    for (int c = 0; c < 16; c += 2) {
        float4 v = *reinterpret_cast<const float4*>(src + 2 * c);
        dst[qpos(c, r)]     = pack_bf(v.x, v.y);
        dst[qpos(c + 1, r)] = pack_bf(v.z, v.w);
    }
}

// ---- phase 1: HMMA GEMM + approximate argmin + margin ----------------------
// smem u32 layout: csq[512] | best1 u64[128] | best2 u64[128] | tiles
constexpr int SM_CSQ  = 0;
constexpr int SM_B1   = 512;    // u64 x 128  (u32 units 512..768)
constexpr int SM_B2   = 768;
constexpr int SM_TILE = 1024;
constexpr int A_U32   = 128 * 16;       // 2048
constexpr int B_U32   = 256 * 16;       // 4096
constexpr int BUF_U32 = A_U32 + B_U32;  // 6144
constexpr int SMEM_BYTES = (SM_TILE + 2 * BUF_U32) * 4;   // 53248

__device__ __forceinline__ void mma_bf16(float* d, uint32_t a0, uint32_t a1,
                                         uint32_t a2, uint32_t a3,
                                         uint32_t b0, uint32_t b1) {
    asm volatile(
        "mma.sync.aligned.m16n8k16.row.col.f32.bf16.bf16.f32 "
        "{%0,%1,%2,%3}, {%4,%5,%6,%7}, {%8,%9}, {%0,%1,%2,%3};"
        : "+f"(d[0]), "+f"(d[1]), "+f"(d[2]), "+f"(d[3])
        : "r"(a0), "r"(a1), "r"(a2), "r"(a3), "r"(b0), "r"(b1));
}

__global__ __launch_bounds__(256)
void encode_main(float* __restrict__ out, int N) {
    extern __shared__ uint32_t smem[];
    float* csq_s = reinterpret_cast<float*>(smem + SM_CSQ);
    unsigned long long* best1u = reinterpret_cast<unsigned long long*>(smem + SM_B1);
    unsigned long long* best2u = reinterpret_cast<unsigned long long*>(smem + SM_B2);
    const uint32_t sb = smem_u32(smem);

    const int tid  = threadIdx.x;
    const int lane = tid & 31, wid = tid >> 5;
    const int g = lane >> 2, tc = lane & 3;
    const int wm = wid >> 2, wn = wid & 3;        // 2 x 4 warp grid
    const int base = blockIdx.x * 128;

    csq_s[tid]       = g_csq[tid];
    csq_s[tid + 256] = g_csq[tid + 256];

    unsigned long long b1 = ~0ull, b2 = ~0ull;    // running (score||col) keys
    float acc[4][8][4];

    for (int nblk = 0; nblk < 2; nblk++) {
        const int nbase = nblk * 256;
        #pragma unroll
        for (int mi = 0; mi < 4; mi++)
            #pragma unroll
            for (int ni = 0; ni < 8; ni++)
                #pragma unroll
                for (int f = 0; f < 4; f++) acc[mi][ni][f] = 0.f;

        // stage(ch, buf): pure cp.async copies of pre-swizzled data
        auto stage = [&](int ch, int buf) {
            const uint32_t aoff = sb + (SM_TILE + buf * BUF_U32) * 4;
            const uint32_t boff = aoff + A_U32 * 4;
            #pragma unroll
            for (int i = 0; i < 2; i++) {         // A: 128 rows x 64B
                int lin = tid + 256 * i;
                int row = lin >> 2, blk = lin & 3;
                CPASYNC16(aoff + row * 64 + blk * 16,
                          (const void*)&g_hbf[(size_t)(base + row) * 512 +
                                              ch * 16 + blk * 4]);
            }
            #pragma unroll
            for (int i = 0; i < 4; i++) {         // B: 256 cw x 64B
                int lin = tid + 256 * i;
                int row = lin >> 2, blk = lin & 3;
                CPASYNC16(boff + row * 64 + blk * 16,
                          (const void*)&g_cbhi[(size_t)(nbase + row) * 512 +
                                               ch * 16 + blk * 4]);
            }
            CPCOMMIT();
        };

        stage(0, 0);
        stage(1, 1);

        for (int ch = 0; ch < 32; ch++) {
            if (ch < 31) asm volatile("cp.async.wait_group 1;" ::: "memory");
            else         asm volatile("cp.async.wait_group 0;" ::: "memory");
            __syncthreads();

            const uint32_t* tb = smem + SM_TILE + (ch & 1) * BUF_U32;
            const uint32_t* Bt = tb + A_U32;
            #pragma unroll
            for (int ks = 0; ks < 2; ks++) {
                const int gran = tc + 4 * ks;
                uint2 Ah[4][2], Bh[8];
                #pragma unroll
                for (int mi = 0; mi < 4; mi++) {
                    int arow = wm * 64 + mi * 16 + g;
                    int idx  = arow * 16 + ((gran ^ (arow & 7)) << 1);
                    Ah[mi][0] = *reinterpret_cast<const uint2*>(tb + idx);
                    Ah[mi][1] = *reinterpret_cast<const uint2*>(tb + idx + 128);
                }
                #pragma unroll
                for (int ni = 0; ni < 8; ni++) {
                    int brow = wn * 64 + ni * 8 + g;
                    int idx  = brow * 16 + ((gran ^ (brow & 7)) << 1);
                    Bh[ni] = *reinterpret_cast<const uint2*>(Bt + idx);
                }
                #pragma unroll
                for (int mi = 0; mi < 4; mi++)
                    #pragma unroll
                    for (int ni = 0; ni < 8; ni++)
                        mma_bf16(acc[mi][ni],
                                 Ah[mi][0].x, Ah[mi][1].x,
                                 Ah[mi][0].y, Ah[mi][1].y,
                                 Bh[ni].x, Bh[ni].y);
            }
            __syncthreads();
            if (ch + 2 < 32) stage(ch + 2, ch & 1);
        }

        // ---- n-block epilogue: best1/best2 via keyed smem atomicMin ----
        if (tid < 128) { best1u[tid] = ~0ull; best2u[tid] = ~0ull; }
        __syncthreads();

        #pragma unroll
        for (int mi = 0; mi < 4; mi++)
            #pragma unroll
            for (int half = 0; half < 2; half++) {
                int row = wm * 64 + mi * 16 + g + 8 * half;
                unsigned long long kmin = ~0ull;
                #pragma unroll
                for (int ni = 0; ni < 8; ni++)
                    #pragma unroll
                    for (int f = 0; f < 2; f++) {
                        int col = nbase + wn * 64 + ni * 8 + 2 * tc + f;
                        float s = 0.5f * csq_s[col] - acc[mi][ni][2 * half + f];
                        uint32_t u = __float_as_uint(s);
                        uint32_t k32 = (u & 0x80000000u) ? ~u : (u | 0x80000000u);
                        unsigned long long key =
                            ((unsigned long long)k32 << 32) | (unsigned)col;
                        if (key < kmin) kmin = key;
                    }
                atomicMin(&best1u[row], kmin);
            }
        __syncthreads();
        #pragma unroll
        for (int mi = 0; mi < 4; mi++)
            #pragma unroll
            for (int half = 0; half < 2; half++) {
                int row = wm * 64 + mi * 16 + g + 8 * half;
                unsigned bcol = (unsigned)(best1u[row] & 0xffffffffu);
                unsigned long long kmin = ~0ull;
                #pragma unroll
                for (int ni = 0; ni < 8; ni++)
                    #pragma unroll
                    for (int f = 0; f < 2; f++) {
                        int col = nbase + wn * 64 + ni * 8 + 2 * tc + f;
                        if ((unsigned)col == bcol) continue;
                        float s = 0.5f * csq_s[col] - acc[mi][ni][2 * half + f];
                        uint32_t u = __float_as_uint(s);
                        uint32_t k32 = (u & 0x80000000u) ? ~u : (u | 0x80000000u);
                        unsigned long long key =
                            ((unsigned long long)k32 << 32) | (unsigned)col;
                        if (key < kmin) kmin = key;
                    }
                atomicMin(&best2u[row], kmin);
            }
        __syncthreads();
        if (tid < 128) {      // merge this n-block's top-2 into running top-2
            unsigned long long c1 = best1u[tid], c2 = best2u[tid];
            if (c1 < b1) { b2 = (b1 < c2 ? b1 : c2); b1 = c1; }
            else         { b2 = (b2 < c1 ? b2 : c1); }
        }
        __syncthreads();
    }

    if (tid < 128) {
        uint32_t h1 = (uint32_t)(b1 >> 32), h2 = (uint32_t)(b2 >> 32);
        float s1 = (h1 & 0x80000000u) ? __uint_as_float(h1 & 0x7fffffffu)
                                      : __uint_as_float(~h1);
        float s2 = (h2 & 0x80000000u) ? __uint_as_float(h2 & 0x7fffffffu)
                                      : __uint_as_float(~h2);
        int row = base + tid;
        out[row]      = (float)(unsigned)(b1 & 0xffffffffu);
        g_margin[row] = s2 - s1;
    }
}

// ---- phase 2: exact fp32 refinement for near-tie rows ----------------------
constexpr float TAU = 1.0f;   // ~14 sigma of the single-term bf16 dot noise

__global__ __launch_bounds__(256)
void refine_kernel(const float* __restrict__ h, const float* __restrict__ cb,
                   float* __restrict__ out, int N) {
    __shared__ float hrow[1024];
    __shared__ float rmin[256];
    __shared__ int   ridx[256];
    const int base = blockIdx.x * 128;
    const int t = threadIdx.x;

    for (int r = 0; r < 128; r++) {
        int row = base + r;
        if (g_margin[row] >= TAU) continue;       // uniform branch
        __syncthreads();
        for (int i = t; i < 1024; i += 256)
            hrow[i] = h[(size_t)row * 1024 + i];
        __syncthreads();

        float best = 3.402823466e+38f;
        int   bidx = 0x7fffffff;
        for (int k = t; k < 512; k += 256) {
            const float* c = cb + (size_t)k * 1024;
            float dot = 0.f;
            for (int d = 0; d < 1024; d += 4) {
                float4 cv = *reinterpret_cast<const float4*>(c + d);
                dot = fmaf(hrow[d],     cv.x, dot);
                dot = fmaf(hrow[d + 1], cv.y, dot);
                dot = fmaf(hrow[d + 2], cv.z, dot);
                dot = fmaf(hrow[d + 3], cv.w, dot);
            }
            float s = 0.5f * g_csq[k] - dot;
            if (s < best || (s == best && k < bidx)) { best = s; bidx = k; }
        }
        rmin[t] = best; ridx[t] = bidx;
        __syncthreads();
        for (int off = 128; off; off >>= 1) {
            if (t < off) {
                float ov = rmin[t + off]; int oi = ridx[t + off];
                if (ov < rmin[t] || (ov == rmin[t] && oi < ridx[t])) {
                    rmin[t] = ov; ridx[t] = oi;
                }
            }
            __syncthreads();
        }
        if (t == 0) out[row] = (float)ridx[0];
    }
}

// ---------------------------------------------------------------------------
extern "C" void kernel_launch(void* const* d_in, const int* in_sizes, int n_in,
                              void* d_out, int out_size) {
    const int D = 1024;
    const float* h;
    const float* cb;
    int N;
    if (in_sizes[0] >= in_sizes[1]) {
        h  = (const float*)d_in[0];  N = in_sizes[0] / D;
        cb = (const float*)d_in[1];
    } else {
        h  = (const float*)d_in[1];  N = in_sizes[1] / D;
        cb = (const float*)d_in[0];
    }
    float* out = (float*)d_out;

    cudaFuncSetAttribute(encode_main,
                         cudaFuncAttributeMaxDynamicSharedMemorySize, SMEM_BYTES);

    prep_cb<<<512, 256>>>(cb);
    prep_h<<<N / 8, 256>>>(h);
    encode_main<<<N / 128, 256, SMEM_BYTES>>>(out, N);
    refine_kernel<<<N / 128, 256>>>(h, cb, out, N);
}

// round 17
// speedup vs baseline: 8.4763x; 8.4763x over previous
#include <cuda_runtime.h>
#include <cuda_bf16.h>
#include <cstdint>

// ---------------------------------------------------------------------------
// SAMMCodebook.encode on GB300 (sm_103a) — single-term bf16 HMMA GEMM that
// streams raw dots to gmem + warp-per-row finalize with windowed exact
// verification.
//   h:[65536,1024]f32, cb:[512,1024]f32 -> float out[65536]
//   argmin_k ||h-c_k||^2 == argmin_k (0.5||c_k||^2 - <h,c_k>)
//
// R16 post-mortem: encode (1-term bf16) was ~210us; refine_kernel was 3.89ms
// because P(top2 gap < 1.0) ~ 22% and the fallback rescored whole rows.
// Fix: verify per-CANDIDATE. True argmin must lie within WIN=2.0 (~28 sigma
// of bf16 dot noise) of the bf16 best; expected candidates-in-window ~ 1.5.
// finalize: warp per row -> min + window via ballot; exact fp32 warp-dot for
// windowed candidates only; full rescore only if >16 candidates (P~0).
// ---------------------------------------------------------------------------

__device__ float    g_csq[512];
__device__ unsigned g_cbhi[512 * 512];         // swizzled bf16 pairs [k][512]
__device__ unsigned g_hbf[65536u * 512u];      // swizzled bf16 pairs [n][512]
__device__ float    g_dot[65536u * 512u];      // bf16-GEMM dots [n][512]

__device__ __forceinline__ uint32_t pack_bf(float a, float b) {
    return (uint32_t)__bfloat16_as_ushort(__float2bfloat16(a)) |
           ((uint32_t)__bfloat16_as_ushort(__float2bfloat16(b)) << 16);
}
// u32 logical col c (0..15) -> stored position, keyed by matrix row.
__device__ __forceinline__ int qpos(int c, int r) {
    int p = ((c & 3) << 1) | ((c >> 2) & 1) | (c & 8);
    return (((p >> 1) ^ (r & 7)) << 1) | (p & 1);
}
__device__ __forceinline__ uint32_t smem_u32(const void* p) {
    uint32_t a;
    asm("{ .reg .u64 t; cvta.to.shared.u64 t, %1; cvt.u32.u64 %0, t; }"
        : "=r"(a) : "l"(p));
    return a;
}
#define CPASYNC16(dst, src) \
    asm volatile("cp.async.cg.shared.global [%0], [%1], 16;" \
                 :: "r"(dst), "l"(src) : "memory")
#define CPCOMMIT() asm volatile("cp.async.commit_group;" ::: "memory")

// ---- phase 0a: csq + swizzled bf16 pack of codebook ------------------------
__global__ void prep_cb(const float* __restrict__ cb) {
    int k = blockIdx.x;
    int t = threadIdx.x;
    float4 v = reinterpret_cast<const float4*>(cb + (size_t)k * 1024)[t];
    float s = v.x * v.x + v.y * v.y + v.z * v.z + v.w * v.w;
    #pragma unroll
    for (int o = 16; o; o >>= 1) s += __shfl_xor_sync(0xffffffffu, s, o);
    __shared__ float ws[8];
    if ((t & 31) == 0) ws[t >> 5] = s;
    __syncthreads();
    if (t == 0) {
        float tot = 0.f;
        #pragma unroll
        for (int w = 0; w < 8; w++) tot += ws[w];
        g_csq[k] = tot;
    }
    #pragma unroll
    for (int it = 0; it < 2; it++) {
        int lin = t + 256 * it;
        int ch = lin >> 4, c = lin & 15;
        float a = cb[(size_t)k * 1024 + 32 * ch + 2 * c];
        float b = cb[(size_t)k * 1024 + 32 * ch + 2 * c + 1];
        g_cbhi[k * 512 + ch * 16 + qpos(c, k)] = pack_bf(a, b);
    }
}

// ---- phase 0b: swizzled bf16 pack of h -------------------------------------
__global__ void prep_h(const float* __restrict__ h) {
    int r  = blockIdx.x * 8 + (threadIdx.x >> 5);
    int ch = threadIdx.x & 31;
    const float* src = h + (size_t)r * 1024 + 32 * ch;
    unsigned* dst = g_hbf + (size_t)r * 512 + ch * 16;
    #pragma unroll
    for (int c = 0; c < 16; c += 2) {
        float4 v = *reinterpret_cast<const float4*>(src + 2 * c);
        dst[qpos(c, r)]     = pack_bf(v.x, v.y);
        dst[qpos(c + 1, r)] = pack_bf(v.z, v.w);
    }
}

// ---- phase 1: HMMA GEMM -> raw dots ---------------------------------------
constexpr int A_U32   = 128 * 16;       // 2048
constexpr int B_U32   = 256 * 16;       // 4096
constexpr int BUF_U32 = A_U32 + B_U32;  // 6144
constexpr int SMEM_BYTES = 2 * BUF_U32 * 4;   // 49152

__device__ __forceinline__ void mma_bf16(float* d, uint32_t a0, uint32_t a1,
                                         uint32_t a2, uint32_t a3,
                                         uint32_t b0, uint32_t b1) {
    asm volatile(
        "mma.sync.aligned.m16n8k16.row.col.f32.bf16.bf16.f32 "
        "{%0,%1,%2,%3}, {%4,%5,%6,%7}, {%8,%9}, {%0,%1,%2,%3};"
        : "+f"(d[0]), "+f"(d[1]), "+f"(d[2]), "+f"(d[3])
        : "r"(a0), "r"(a1), "r"(a2), "r"(a3), "r"(b0), "r"(b1));
}

__global__ __launch_bounds__(256)
void encode_main(int N) {
    extern __shared__ uint32_t smem[];
    const uint32_t sb = smem_u32(smem);

    const int tid  = threadIdx.x;
    const int lane = tid & 31, wid = tid >> 5;
    const int g = lane >> 2, tc = lane & 3;
    const int wm = wid >> 2, wn = wid & 3;        // 2 x 4 warp grid
    const int base = blockIdx.x * 128;

    float acc[4][8][4];

    for (int nblk = 0; nblk < 2; nblk++) {
        const int nbase = nblk * 256;
        #pragma unroll
        for (int mi = 0; mi < 4; mi++)
            #pragma unroll
            for (int ni = 0; ni < 8; ni++)
                #pragma unroll
                for (int f = 0; f < 4; f++) acc[mi][ni][f] = 0.f;

        auto stage = [&](int ch, int buf) {
            const uint32_t aoff = sb + (buf * BUF_U32) * 4;
            const uint32_t boff = aoff + A_U32 * 4;
            #pragma unroll
            for (int i = 0; i < 2; i++) {         // A: 128 rows x 64B
                int lin = tid + 256 * i;
                int row = lin >> 2, blk = lin & 3;
                CPASYNC16(aoff + row * 64 + blk * 16,
                          (const void*)&g_hbf[(size_t)(base + row) * 512 +
                                              ch * 16 + blk * 4]);
            }
            #pragma unroll
            for (int i = 0; i < 4; i++) {         // B: 256 cw x 64B
                int lin = tid + 256 * i;
                int row = lin >> 2, blk = lin & 3;
                CPASYNC16(boff + row * 64 + blk * 16,
                          (const void*)&g_cbhi[(size_t)(nbase + row) * 512 +
                                               ch * 16 + blk * 4]);
            }
            CPCOMMIT();
        };

        stage(0, 0);
        stage(1, 1);

        for (int ch = 0; ch < 32; ch++) {
            if (ch < 31) asm volatile("cp.async.wait_group 1;" ::: "memory");
            else         asm volatile("cp.async.wait_group 0;" ::: "memory");
            __syncthreads();

            const uint32_t* tb = smem + (ch & 1) * BUF_U32;
            const uint32_t* Bt = tb + A_U32;
            #pragma unroll
            for (int ks = 0; ks < 2; ks++) {
                const int gran = tc + 4 * ks;
                uint2 Ah[4][2], Bh[8];
                #pragma unroll
                for (int mi = 0; mi < 4; mi++) {
                    int arow = wm * 64 + mi * 16 + g;
                    int idx  = arow * 16 + ((gran ^ (arow & 7)) << 1);
                    Ah[mi][0] = *reinterpret_cast<const uint2*>(tb + idx);
                    Ah[mi][1] = *reinterpret_cast<const uint2*>(tb + idx + 128);
                }
                #pragma unroll
                for (int ni = 0; ni < 8; ni++) {
                    int brow = wn * 64 + ni * 8 + g;
                    int idx  = brow * 16 + ((gran ^ (brow & 7)) << 1);
                    Bh[ni] = *reinterpret_cast<const uint2*>(Bt + idx);
                }
                #pragma unroll
                for (int mi = 0; mi < 4; mi++)
                    #pragma unroll
                    for (int ni = 0; ni < 8; ni++)
                        mma_bf16(acc[mi][ni],
                                 Ah[mi][0].x, Ah[mi][1].x,
                                 Ah[mi][0].y, Ah[mi][1].y,
                                 Bh[ni].x, Bh[ni].y);
            }
            __syncthreads();
            if (ch + 2 < 32) stage(ch + 2, ch & 1);
        }

        // ---- stream raw dots to gmem (no reductions here) ----
        #pragma unroll
        for (int mi = 0; mi < 4; mi++)
            #pragma unroll
            for (int half = 0; half < 2; half++) {
                int row = base + wm * 64 + mi * 16 + g + 8 * half;
                float* dst = g_dot + (size_t)row * 512 + nbase + wn * 64 + 2 * tc;
                #pragma unroll
                for (int ni = 0; ni < 8; ni++) {
                    float2 v = make_float2(acc[mi][ni][2 * half],
                                           acc[mi][ni][2 * half + 1]);
                    *reinterpret_cast<float2*>(dst + ni * 8) = v;
                }
            }
    }
}

// ---- phase 2: warp-per-row argmin + windowed exact verification ------------
constexpr float WIN = 2.0f;   // ~28 sigma of bf16 dot noise

__global__ __launch_bounds__(256)
void finalize(const float* __restrict__ h, const float* __restrict__ cb,
              float* __restrict__ out, int N) {
    const int lane = threadIdx.x & 31;
    const int row  = blockIdx.x * 8 + (threadIdx.x >> 5);
    const float* drow = g_dot + (size_t)row * 512;

    // bf16 scores for this lane's 16 columns: col = 4*(lane + 32*j) + c
    float sc[16];
    unsigned long long key = ~0ull;
    #pragma unroll
    for (int j = 0; j < 4; j++) {
        int c0 = 4 * (lane + 32 * j);
        float4 dv = *reinterpret_cast<const float4*>(drow + c0);
        float4 cq = *reinterpret_cast<const float4*>(g_csq + c0);
        float s0 = 0.5f * cq.x - dv.x, s1 = 0.5f * cq.y - dv.y;
        float s2 = 0.5f * cq.z - dv.z, s3 = 0.5f * cq.w - dv.w;
        sc[4 * j] = s0; sc[4 * j + 1] = s1; sc[4 * j + 2] = s2; sc[4 * j + 3] = s3;
        #pragma unroll
        for (int c = 0; c < 4; c++) {
            float s = sc[4 * j + c];
            uint32_t u = __float_as_uint(s);
            uint32_t k32 = (u & 0x80000000u) ? ~u : (u | 0x80000000u);
            unsigned long long k = ((unsigned long long)k32 << 32) |
                                   (unsigned)(c0 + c);
            if (k < key) key = k;
        }
    }
    #pragma unroll
    for (int o = 16; o; o >>= 1) {
        unsigned long long ok = __shfl_xor_sync(0xffffffffu, key, o);
        if (ok < key) key = ok;
    }
    uint32_t h1 = (uint32_t)(key >> 32);
    float s1 = (h1 & 0x80000000u) ? __uint_as_float(h1 & 0x7fffffffu)
                                  : __uint_as_float(~h1);
    int bestcol = (int)(unsigned)(key & 0xffffffffu);

    // windowed candidate mask (includes the best itself)
    float win = s1 + WIN;
    unsigned cmask = 0;
    #pragma unroll
    for (int e = 0; e < 16; e++)
        if (sc[e] <= win) cmask |= (1u << e);
    int total = __reduce_add_sync(0xffffffffu, __popc(cmask));

    if (total > 1) {
        // h row fragments: lane covers floats [4*lane + 128*t, +4)
        float4 hv[8];
        const float* hrow = h + (size_t)row * 1024;
        #pragma unroll
        for (int t = 0; t < 8; t++)
            hv[t] = *reinterpret_cast<const float4*>(hrow + 4 * lane + 128 * t);

        float bsx = 3.402823466e+38f;
        int   bcx = 0x7fffffff;
        auto exact = [&](int col) {
            const float* c = cb + (size_t)col * 1024;
            float d = 0.f;
            #pragma unroll
            for (int t = 0; t < 8; t++) {
                float4 cv = *reinterpret_cast<const float4*>(c + 4 * lane + 128 * t);
                d = fmaf(hv[t].x, cv.x, d);
                d = fmaf(hv[t].y, cv.y, d);
                d = fmaf(hv[t].z, cv.z, d);
                d = fmaf(hv[t].w, cv.w, d);
            }
            #pragma unroll
            for (int o = 16; o; o >>= 1) d += __shfl_xor_sync(0xffffffffu, d, o);
            float sx = 0.5f * g_csq[col] - d;
            if (sx < bsx || (sx == bsx && col < bcx)) { bsx = sx; bcx = col; }
        };

        if (total <= 16) {
            for (int l = 0; l < 32; l++) {
                unsigned m = __shfl_sync(0xffffffffu, cmask, l);
                while (m) {
                    int e = __ffs(m) - 1; m &= m - 1;
                    exact(4 * (l + 32 * (e >> 2)) + (e & 3));
                }
            }
        } else {
            for (int k = 0; k < 512; k++) exact(k);   // paranoia path
        }
        bestcol = bcx;
    }

    if (lane == 0) out[row] = (float)bestcol;
}

// ---------------------------------------------------------------------------
extern "C" void kernel_launch(void* const* d_in, const int* in_sizes, int n_in,
                              void* d_out, int out_size) {
    const int D = 1024;
    const float* h;
    const float* cb;
    int N;
    if (in_sizes[0] >= in_sizes[1]) {
        h  = (const float*)d_in[0];  N = in_sizes[0] / D;
        cb = (const float*)d_in[1];
    } else {
        h  = (const float*)d_in[1];  N = in_sizes[1] / D;
        cb = (const float*)d_in[0];
    }
    float* out = (float*)d_out;

    cudaFuncSetAttribute(encode_main,
                         cudaFuncAttributeMaxDynamicSharedMemorySize, SMEM_BYTES);

    prep_cb<<<512, 256>>>(cb);
    prep_h<<<N / 8, 256>>>(h);
    encode_main<<<N / 128, 256, SMEM_BYTES>>>(N);
    finalize<<<N / 8, 256>>>(h, cb, out, N);
}